// round 10
// baseline (speedup 1.0000x reference)
#include <cuda_runtime.h>
#include <cuda_fp16.h>
#include <mma.h>
#include <stdint.h>
#include <math.h>

using namespace nvcuda;

#define NT 1024
#define HD 128
#define ED 64
#define SC 32
#define PP 32
#define B1D 512
#define B2D 1024
#define M1D 1024
#define TS 12
#define KM1 (HD + B2D)   // 1152
#define BN_INV_F 0.9999950000374997f

// ---------------- device state / scratch ----------------
static __device__ float g_h[NT * HD];
static __device__ float g_c[NT * HD];
static __device__ float g_h2[NT * HD];
static __device__ float g_lp[NT * 2];
static __device__ float g_din[NT * ED];
static __device__ float g_hpre[NT * B1D];
static __device__ float g_hp[4 * NT * HD];     // m2 split-K partials
// folded scalar weights
static __device__ float g_A[B1D], g_B[B1D], g_bias1[B1D];
static __device__ float g_Wb[B1D * HD];
static __device__ float g_bias2[B2D], g_bm1[M1D], g_bm2[HD];
static __device__ float g_LW[4 * HD * 192], g_Lb[4 * HD];
// pre-tiled fp16 weights: [nb][chunk64][128r x 64k] tiles (8192 halfs)
static __device__ __half g_W2th[8 * 8 * 8192];
static __device__ __half g_M1th[8 * 18 * 8192];
static __device__ __half g_M2th[16 * 8192];
// activation tiles, fp16, [group][chunk64][128x64]
static __device__ __half g_x1h[256 * 8 * 8192];   // pool A
static __device__ __half g_mAh[8 * 18 * 8192];    // m1 A
static __device__ __half g_mBh[8 * 16 * 8192];    // m2 A

// ---------------- helpers ----------------
__device__ __forceinline__ uint32_t pack2hf(float v0, float v1) {
    __half2 h = __floats2half2_rn(v0, v1);
    return *(uint32_t*)&h;
}
__device__ __forceinline__ uint32_t smem_u32(const void* p) {
    uint32_t a;
    asm("{ .reg .u64 t; cvta.to.shared.u64 t, %1; cvt.u32.u64 %0, t; }" : "=r"(a) : "l"(p));
    return a;
}
__device__ __forceinline__ void cpa(uint32_t dsmem, const void* gsrc) {
    asm volatile("cp.async.cg.shared.global [%0], [%1], 16;" :: "r"(dsmem), "l"(gsrc) : "memory");
}
#define CPA_COMMIT() asm volatile("cp.async.commit_group;" ::: "memory")
#define CPA_WAIT1()  asm volatile("cp.async.wait_group 1;" ::: "memory")
#define CPA_WAIT0()  asm volatile("cp.async.wait_group 0;" ::: "memory")

// ---------------- prep kernels (once per launch) ----------------
__global__ void init_state(const float* __restrict__ h0, const float* __restrict__ c0,
                           const float* __restrict__ last_pos, const float* __restrict__ last_pos_rel,
                           const float* __restrict__ embW, const float* __restrict__ embb) {
    int idx = blockIdx.x * blockDim.x + threadIdx.x;
    if (idx < NT * HD) { g_h[idx] = h0[idx]; g_c[idx] = c0[idx]; }
    if (idx < NT * 2) g_lp[idx] = last_pos[idx];
    if (idx < NT * ED) {
        int n = idx / ED, e = idx % ED;
        g_din[idx] = last_pos_rel[n * 2] * embW[e * 2] +
                     last_pos_rel[n * 2 + 1] * embW[e * 2 + 1] + embb[e];
    }
}

__global__ void fold_pp1(const float* __restrict__ pp1_W, const float* __restrict__ pp1_b,
                         const float* __restrict__ pp1_g, const float* __restrict__ pp1_be,
                         const float* __restrict__ sp_W, const float* __restrict__ sp_b) {
    int k = blockIdx.x * blockDim.x + threadIdx.x;
    if (k >= B1D) return;
    float s1 = BN_INV_F * pp1_g[k];
    const float* row = pp1_W + (size_t)k * (ED + HD);
    float sa = 0.f, sb = 0.f, sc = 0.f;
    for (int e = 0; e < ED; e++) {
        float w = row[e];
        sa += w * sp_W[e * 2]; sb += w * sp_W[e * 2 + 1]; sc += w * sp_b[e];
    }
    g_A[k] = sa * s1; g_B[k] = sb * s1;
    g_bias1[k] = (pp1_b[k] + sc) * s1 + pp1_be[k];
    for (int h = 0; h < HD; h++) g_Wb[k * HD + h] = row[ED + h] * s1;
}

__global__ void fold_LW(const float* __restrict__ Wih, const float* __restrict__ Whh,
                        const float* __restrict__ bih, const float* __restrict__ bhh) {
    for (int idx = blockIdx.x * blockDim.x + threadIdx.x; idx < 512 * 192; idx += gridDim.x * blockDim.x) {
        int r = idx / 192, cc = idx % 192;
        g_LW[idx] = (cc < 64) ? Wih[r * 64 + cc] : Whh[r * 128 + cc - 64];
        if (cc == 0) g_Lb[r] = bih[r] + bhh[r];
    }
}

// fp16 pre-tiled weights. WM=0: W2(K=512), 1: m1(K=1152), 2: m2(K=1024,R=128)
template <int WM>
__global__ void prep_wB(const float* __restrict__ W, const float* __restrict__ b,
                        const float* __restrict__ g, const float* __restrict__ be) {
    constexpr int K = (WM == 0) ? B1D : (WM == 1) ? KM1 : M1D;
    constexpr int ROWS = (WM == 2) ? HD : 1024;
    constexpr int KC = K / 64;
    __half* oh = (WM == 0) ? g_W2th : (WM == 1) ? g_M1th : g_M2th;
    float* bo = (WM == 0) ? g_bias2 : (WM == 1) ? g_bm1 : g_bm2;
    int total = ROWS * (K / 2);
    for (int p = blockIdx.x * blockDim.x + threadIdx.x; p < total; p += gridDim.x * blockDim.x) {
        int co = p / (K / 2), kp = p % (K / 2), k = kp * 2;
        int nb = co >> 7, r = co & 127, c = k >> 6;
        float s = BN_INV_F * g[co];
        float v0 = W[(size_t)co * K + k] * s, v1 = W[(size_t)co * K + k + 1] * s;
        size_t woff = (size_t)(nb * KC + c) * 4096 + r * 32 + (kp & 31);
        ((uint32_t*)oh)[woff] = pack2hf(v0, v1);
        if (kp == 0) bo[co] = b[co] * s + be[co];
    }
}

// ---------------- fused gates GEMM + LSTM pointwise ----------------
// grid 32 CTAs x 256 thr; CTA = 32 peds. Gates kept in smem; pointwise + pos head +
// din update + h2 pack (m1 A chunks 0..1) fused.
#define GL_SG   0          // sg: 32 x 520
#define GL_AS   (32*520)   // a_s: 32 x 193
#define GL_WS   (GL_AS + 32*193)   // w_s: 64 x 129
#define GL_HS   (GL_WS + 64*129)   // hsm: 32 x 136
#define GL_RP   (GL_HS + 32*136)   // rps: 32 x 2
#define GL_TOT  (GL_RP + 64)

template <int FIRST>
__global__ __launch_bounds__(256) void gates_lstm(
    const float* __restrict__ posW, const float* __restrict__ posb,
    const float* __restrict__ embW, const float* __restrict__ embb,
    float* __restrict__ out_t) {
    extern __shared__ float sm[];
    float* sg  = sm + GL_SG;
    float* a_s = sm + GL_AS;
    float* w_s = sm + GL_WS;
    float* hsm = sm + GL_HS;
    float* rps = sm + GL_RP;
    int tid = threadIdx.x;
    int nbase = blockIdx.x * 32;
    int tx = tid & 31, ty = tid >> 5;

    // stage A (32 peds x 192): [din | h]
    for (int idx = tid; idx < 32 * 192; idx += 256) {
        int j = idx / 192, kk = idx % 192;
        int ped = nbase + j;
        float v;
        if (kk < 64) v = g_din[ped * ED + kk];
        else {
            int cc = kk - 64;
            if (FIRST) v = g_h[ped * HD + cc];
            else {
                float sum = g_hp[(size_t)ped * HD + cc]
                          + g_hp[(size_t)(NT + ped) * HD + cc]
                          + g_hp[(size_t)(2 * NT + ped) * HD + cc]
                          + g_hp[(size_t)(3 * NT + ped) * HD + cc];
                v = fmaxf(sum + g_bm2[cc], 0.f);
            }
        }
        a_s[j * 193 + kk] = v;
    }

    // gates GEMM: 32 x 512, K=192, into sg
    for (int cb = 0; cb < 4; cb++) {
        float acc[4][4] = {};
        for (int k0 = 0; k0 < 192; k0 += 64) {
            __syncthreads();
            for (int idx = tid; idx < 128 * 64; idx += 256) {
                int c = idx >> 6, k = idx & 63;
                w_s[k * 129 + c] = g_LW[(size_t)(cb * 128 + c) * 192 + k0 + k];
            }
            __syncthreads();
#pragma unroll 4
            for (int k = 0; k < 64; k++) {
                float xr[4], wr[4];
#pragma unroll
                for (int jj = 0; jj < 4; jj++) xr[jj] = a_s[(ty + jj * 8) * 193 + k0 + k];
#pragma unroll
                for (int cc = 0; cc < 4; cc++) wr[cc] = w_s[k * 129 + tx + cc * 32];
#pragma unroll
                for (int jj = 0; jj < 4; jj++)
#pragma unroll
                    for (int cc = 0; cc < 4; cc++) acc[jj][cc] = fmaf(xr[jj], wr[cc], acc[jj][cc]);
            }
        }
#pragma unroll
        for (int jj = 0; jj < 4; jj++)
#pragma unroll
            for (int cc = 0; cc < 4; cc++) {
                int col = cb * 128 + tx + cc * 32;
                sg[(ty + jj * 8) * 520 + col] = acc[jj][cc] + g_Lb[col];
            }
    }
    __syncthreads();

    // LSTM pointwise: 8 threads per ped
    {
        int pl = tid >> 3, l8 = tid & 7;
        int ped = nbase + pl;
        float r0 = 0.f, r1 = 0.f;
#pragma unroll
        for (int q = 0; q < 16; q++) {
            int t = l8 + 8 * q;
            float gi = sg[pl * 520 + t];
            float gf = sg[pl * 520 + 128 + t];
            float gg = sg[pl * 520 + 256 + t];
            float go = sg[pl * 520 + 384 + t];
            float ig = 1.f / (1.f + expf(-gi));
            float fg = 1.f / (1.f + expf(-gf));
            float gv = tanhf(gg);
            float og = 1.f / (1.f + expf(-go));
            float c2 = fg * g_c[ped * HD + t] + ig * gv;
            float h2 = og * tanhf(c2);
            g_c[ped * HD + t] = c2;
            hsm[pl * 136 + t] = h2;
            r0 = fmaf(h2, posW[t], r0);
            r1 = fmaf(h2, posW[HD + t], r1);
        }
        r0 += __shfl_xor_sync(0xffffffffu, r0, 1);
        r0 += __shfl_xor_sync(0xffffffffu, r0, 2);
        r0 += __shfl_xor_sync(0xffffffffu, r0, 4);
        r1 += __shfl_xor_sync(0xffffffffu, r1, 1);
        r1 += __shfl_xor_sync(0xffffffffu, r1, 2);
        r1 += __shfl_xor_sync(0xffffffffu, r1, 4);
        if (l8 == 0) {
            float v0 = r0 + posb[0], v1 = r1 + posb[1];
            rps[pl * 2] = v0; rps[pl * 2 + 1] = v1;
            out_t[ped * 2] = v0; out_t[ped * 2 + 1] = v1;
            g_lp[ped * 2] += v0; g_lp[ped * 2 + 1] += v1;
        }
    }
    __syncthreads();

    // din update + h2 pack into m1 A chunks 0..1
    for (int idx = tid; idx < 2048; idx += 256) {
        int pl = idx >> 6, e = idx & 63;
        int ped = nbase + pl;
        float v0r = rps[pl * 2], v1r = rps[pl * 2 + 1];
        g_din[ped * ED + e] = fmaf(v0r, embW[e * 2], fmaf(v1r, embW[e * 2 + 1], embb[e]));
        float h0 = hsm[pl * 136 + 2 * e], h1 = hsm[pl * 136 + 2 * e + 1];
        int mb = ped >> 7, m = ped & 127, c = e >> 5;
        ((uint32_t*)g_mAh)[(size_t)(mb * 18 + c) * 4096 + m * 32 + (e & 31)] = pack2hf(h0, h1);
    }
    for (int idx = tid; idx < 4096; idx += 256) {
        int pl = idx >> 7, t = idx & 127;
        g_h2[(nbase + pl) * HD + t] = hsm[pl * 136 + t];
    }
}

// ---------------- SIMT GEMM: hpre = h2 @ Wb^T + bias1 (K=128) ----------------
__global__ __launch_bounds__(256) void hpre_gemm() {
    int c0 = blockIdx.x * 128, grp = blockIdx.y, tid = threadIdx.x;
    int tx = tid & 31, ty = tid >> 5;
    __shared__ float a_s[32][64];
    __shared__ float w_s[64][129];
    int nbase = grp * 32;
    float acc[4][4] = {};
    for (int k0 = 0; k0 < HD; k0 += 64) {
        __syncthreads();
        for (int idx = tid; idx < 32 * 64; idx += 256) {
            int j = idx >> 6, k = idx & 63;
            a_s[j][k] = g_h2[(nbase + j) * HD + k0 + k];
        }
        for (int idx = tid; idx < 128 * 64; idx += 256) {
            int c = idx >> 6, k = idx & 63;
            w_s[k][c] = g_Wb[(size_t)(c0 + c) * HD + k0 + k];
        }
        __syncthreads();
#pragma unroll 4
        for (int k = 0; k < 64; k++) {
            float xr[4], wr[4];
#pragma unroll
            for (int jj = 0; jj < 4; jj++) xr[jj] = a_s[ty + jj * 8][k];
#pragma unroll
            for (int cc = 0; cc < 4; cc++) wr[cc] = w_s[k][tx + cc * 32];
#pragma unroll
            for (int jj = 0; jj < 4; jj++)
#pragma unroll
                for (int cc = 0; cc < 4; cc++) acc[jj][cc] = fmaf(xr[jj], wr[cc], acc[jj][cc]);
        }
    }
#pragma unroll
    for (int jj = 0; jj < 4; jj++) {
        int n = nbase + ty + jj * 8;
#pragma unroll
        for (int cc = 0; cc < 4; cc++) {
            int c = c0 + tx + cc * 32;
            g_hpre[(size_t)n * B1D + c] = acc[jj][cc] + g_bias1[c];
        }
    }
}

// ---------------- build x1 fp16 tiles (once per step) ----------------
__global__ __launch_bounds__(256) void build_x1() {
    int c = blockIdx.x, ib = blockIdx.y, s = blockIdx.z;
    int tid = threadIdx.x;
    __shared__ float rxs[128], rys[128];
    if (tid < 128) {
        int i = ib * 4 + (tid >> 5), j = tid & 31;
        float dx = g_lp[(s * 32 + j) * 2]     - g_lp[(s * 32 + i) * 2];
        float dy = g_lp[(s * 32 + j) * 2 + 1] - g_lp[(s * 32 + i) * 2 + 1];
        float nrm = fmaxf(sqrtf(dx * dx + dy * dy), 1e-12f);
        rxs[tid] = dx / nrm; rys[tid] = dy / nrm;
    }
    __syncthreads();
    int grp = s * 8 + ib;
    uint32_t* oh = (uint32_t*)g_x1h + (size_t)(grp * 8 + c) * 4096;
    int kp = tid & 31, k = c * 64 + kp * 2;
    float2 ab0 = *(const float2*)(g_A + k);
    float2 bb0 = *(const float2*)(g_B + k);
#pragma unroll
    for (int q = 0; q < 16; q++) {
        int m = (tid >> 5) + q * 8;
        int pj = s * 32 + (m & 31);
        float rx = rxs[m], ry = rys[m];
        float2 hp = *(const float2*)(g_hpre + (size_t)pj * B1D + k);
        float v0 = fmaxf(hp.x + rx * ab0.x + ry * bb0.x, 0.f);
        float v1 = fmaxf(hp.y + rx * ab0.y + ry * bb0.y, 0.f);
        oh[m * 32 + kp] = pack2hf(v0, v1);
    }
}

// ---------------- pool wmma GEMM: M=128 (1 grp), N=256 (2 W tiles) ----------------
// grid(4 nbp, 256 grpY); KC=16 k32 chunks; warp tile 32x128 (4 wr x 2 wc).
#define POOL_SS 30720      // stage: A 10240 + W 20480
#define POOL_SMEM 69632    // max(2*POOL_SS, c_s 128*136*4)

__global__ __launch_bounds__(256) void pool_gemm() {
    extern __shared__ __align__(16) char smraw[];
    uint32_t base = smem_u32(smraw);
    float* c_s = (float*)smraw;
    int tid = threadIdx.x, w = tid >> 5;
    int wr = w >> 1, wc = w & 1;
    int nbp = blockIdx.x, grpY = blockIdx.y;

    auto stage = [&](int buf, int c) {
        int ch = c >> 1, sub = c & 1;
        uint32_t sb = base + buf * POOL_SS;
        const __half* At = g_x1h + (size_t)(grpY * 8 + ch) * 8192;
        for (int i = tid; i < 512; i += 256) {
            int r = i >> 2, seg = i & 3;
            cpa(sb + r * 80 + seg * 16, At + r * 64 + sub * 32 + seg * 8);
        }
        for (int i = tid; i < 1024; i += 256) {
            int r = i >> 2, seg = i & 3;
            int half = r >> 7, rl = r & 127;
            cpa(sb + 10240 + r * 80 + seg * 16,
                g_W2th + (size_t)((nbp * 2 + half) * 8 + ch) * 8192 + rl * 64 + sub * 32 + seg * 8);
        }
        CPA_COMMIT();
    };

    wmma::fragment<wmma::accumulator, 16, 16, 16, float> acc[2][8];
#pragma unroll
    for (int mf = 0; mf < 2; mf++)
#pragma unroll
        for (int nf = 0; nf < 8; nf++) wmma::fill_fragment(acc[mf][nf], 0.f);

    stage(0, 0);
    for (int c = 0; c < 16; c++) {
        if (c + 1 < 16) { stage((c + 1) & 1, c + 1); CPA_WAIT1(); } else { CPA_WAIT0(); }
        __syncthreads();
        const __half* sbuf = (const __half*)(smraw + (c & 1) * POOL_SS);
        const __half* whp = sbuf + 5120;
#pragma unroll
        for (int ks = 0; ks < 2; ks++) {
            wmma::fragment<wmma::matrix_a, 16, 16, 16, __half, wmma::row_major> af[2];
#pragma unroll
            for (int mf = 0; mf < 2; mf++)
                wmma::load_matrix_sync(af[mf], sbuf + (wr * 32 + mf * 16) * 40 + ks * 16, 40);
#pragma unroll
            for (int nf = 0; nf < 8; nf++) {
                wmma::fragment<wmma::matrix_b, 16, 16, 16, __half, wmma::col_major> bh;
                wmma::load_matrix_sync(bh, whp + (wc * 128 + nf * 16) * 40 + ks * 16, 40);
#pragma unroll
                for (int mf = 0; mf < 2; mf++)
                    wmma::mma_sync(acc[mf][nf], af[mf], bh, acc[mf][nf]);
            }
        }
        __syncthreads();
    }

    // epilogue: two 128-col phases through c_s; max over j, relu(+bias2), pack into m1 A
    int s = grpY >> 3, ib = grpY & 7;
    for (int ph = 0; ph < 2; ph++) {
        __syncthreads();
        if (wc == ph) {
#pragma unroll
            for (int mf = 0; mf < 2; mf++)
#pragma unroll
                for (int nf = 0; nf < 8; nf++)
                    wmma::store_matrix_sync(c_s + (wr * 32 + mf * 16) * 136 + nf * 16,
                                            acc[mf][nf], 136, wmma::mem_row_major);
        }
        __syncthreads();
        {
            int il = tid >> 6, kp0 = tid & 63, cc0 = kp0 * 2;
            float m0 = c_s[(il * 32) * 136 + cc0];
            float m1v = c_s[(il * 32) * 136 + cc0 + 1];
#pragma unroll 8
            for (int r = 1; r < 32; r++) {
                m0  = fmaxf(m0,  c_s[(il * 32 + r) * 136 + cc0]);
                m1v = fmaxf(m1v, c_s[(il * 32 + r) * 136 + cc0 + 1]);
            }
            int col = nbp * 256 + ph * 128 + cc0;
            float v0 = fmaxf(m0 + g_bias2[col], 0.f);
            float v1 = fmaxf(m1v + g_bias2[col + 1], 0.f);
            int ped = s * 32 + ib * 4 + il;
            int mb = ped >> 7, m = ped & 127;
            int cch = 2 + (col >> 6);
            ((uint32_t*)g_mAh)[(size_t)(mb * 18 + cch) * 4096 + m * 32 + (kp0 & 31)] =
                pack2hf(v0, v1);
        }
    }
}

// ---------------- m1 / m2 wmma GEMM (unchanged from R9) ----------------
// GM=1: m1, grid(8 nb, 16), ROWS=64, KC=36, warp tile 32x32
// GM=2: m2, grid(4 ksl, 8), ROWS=128, KC=8, warp tile 32x64, partials to g_hp
template <int GM>
__global__ __launch_bounds__(256) void wmma_gemm() {
    constexpr int KC = (GM == 1) ? 36 : 8;
    constexpr int ROWS = (GM == 1) ? 64 : 128;
    constexpr int NF = (GM == 1) ? 2 : 4;
    constexpr int WC = (GM == 1) ? 4 : 2;
    constexpr int SA = ROWS * 80;
    constexpr int SS = SA + 10240;
    extern __shared__ __align__(16) char smraw[];
    uint32_t base = smem_u32(smraw);
    float* c_s = (float*)smraw;

    int tid = threadIdx.x, w = tid >> 5;
    int wr = w / WC, wc = w % WC;
    int nbX = blockIdx.x, grpY = blockIdx.y;

    const __half* Ah_g = (GM == 1) ? g_mAh : g_mBh;
    const __half* Wh_g = (GM == 1) ? g_M1th : g_M2th;

    auto stage = [&](int buf, int c) {
        int tile0, sub, roff = 0, wtile;
        if (GM == 1) {
            int ch = c >> 1; sub = c & 1;
            tile0 = (grpY >> 1) * 18 + ch; roff = (grpY & 1) * 64;
            wtile = nbX * 18 + ch;
        } else {
            int gch = nbX * 8 + c; sub = gch & 1;
            tile0 = grpY * 16 + (gch >> 1);
            wtile = gch >> 1;
        }
        uint32_t sb = base + buf * SS;
        for (int i = tid; i < ROWS * 4; i += 256) {
            int r = i >> 2, seg = i & 3;
            size_t so = (size_t)tile0 * 8192 + (roff + r) * 64 + sub * 32 + seg * 8;
            cpa(sb + r * 80 + seg * 16, Ah_g + so);
        }
        for (int i = tid; i < 512; i += 256) {
            int r = i >> 2, seg = i & 3;
            size_t so = (size_t)wtile * 8192 + r * 64 + sub * 32 + seg * 8;
            cpa(sb + SA + r * 80 + seg * 16, Wh_g + so);
        }
        CPA_COMMIT();
    };

    wmma::fragment<wmma::accumulator, 16, 16, 16, float> acc[2][NF];
#pragma unroll
    for (int mf = 0; mf < 2; mf++)
#pragma unroll
        for (int nf = 0; nf < NF; nf++) wmma::fill_fragment(acc[mf][nf], 0.f);

    stage(0, 0);
    for (int c = 0; c < KC; c++) {
        if (c + 1 < KC) { stage((c + 1) & 1, c + 1); CPA_WAIT1(); } else { CPA_WAIT0(); }
        __syncthreads();
        const __half* sbuf = (const __half*)(smraw + (c & 1) * SS);
        const __half* whp = sbuf + SA / 2;
#pragma unroll
        for (int ks = 0; ks < 2; ks++) {
            wmma::fragment<wmma::matrix_a, 16, 16, 16, __half, wmma::row_major> af[2];
#pragma unroll
            for (int mf = 0; mf < 2; mf++)
                wmma::load_matrix_sync(af[mf], sbuf + (wr * 32 + mf * 16) * 40 + ks * 16, 40);
#pragma unroll
            for (int nf = 0; nf < NF; nf++) {
                wmma::fragment<wmma::matrix_b, 16, 16, 16, __half, wmma::col_major> bh;
                wmma::load_matrix_sync(bh, whp + (wc * NF * 16 + nf * 16) * 40 + ks * 16, 40);
#pragma unroll
                for (int mf = 0; mf < 2; mf++)
                    wmma::mma_sync(acc[mf][nf], af[mf], bh, acc[mf][nf]);
            }
        }
        __syncthreads();
    }

    __syncthreads();
#pragma unroll
    for (int mf = 0; mf < 2; mf++)
#pragma unroll
        for (int nf = 0; nf < NF; nf++)
            wmma::store_matrix_sync(c_s + (wr * 32 + mf * 16) * 136 + wc * NF * 16 + nf * 16,
                                    acc[mf][nf], 136, wmma::mem_row_major);
    __syncthreads();

    if (GM == 1) {
        for (int p = tid; p < 4096; p += 256) {
            int r = p >> 6, kp = p & 63;
            int cc0 = kp * 2, col = nbX * 128 + cc0;
            float v0 = fmaxf(c_s[r * 136 + cc0]     + g_bm1[col], 0.f);
            float v1 = fmaxf(c_s[r * 136 + cc0 + 1] + g_bm1[col + 1], 0.f);
            int ped = grpY * 64 + r;
            int mb = ped >> 7, m = ped & 127;
            int cch = nbX * 2 + (kp >> 5);
            ((uint32_t*)g_mBh)[(size_t)(mb * 16 + cch) * 4096 + m * 32 + (kp & 31)] =
                pack2hf(v0, v1);
        }
    } else {
        float* dst = g_hp + (size_t)nbX * NT * HD + (size_t)grpY * 128 * HD;
        for (int p = tid; p < 16384; p += 256) {
            int r = p >> 7, cc = p & 127;
            dst[r * HD + cc] = c_s[r * 136 + cc];
        }
    }
}

// ---------------- host launch ----------------
extern "C" void kernel_launch(void* const* d_in, const int* in_sizes, int n_in,
                              void* d_out, int out_size) {
    const float* last_pos     = (const float*)d_in[0];
    const float* last_pos_rel = (const float*)d_in[1];
    const float* h0  = (const float*)d_in[2];
    const float* c0  = (const float*)d_in[3];
    const float* emb_W = (const float*)d_in[5];
    const float* emb_b = (const float*)d_in[6];
    const float* Wih = (const float*)d_in[7];
    const float* Whh = (const float*)d_in[8];
    const float* bih = (const float*)d_in[9];
    const float* bhh = (const float*)d_in[10];
    const float* pos_W = (const float*)d_in[11];
    const float* pos_b = (const float*)d_in[12];
    const float* sp_W = (const float*)d_in[13];
    const float* sp_b = (const float*)d_in[14];
    const float* pp1_W = (const float*)d_in[15];
    const float* pp1_b = (const float*)d_in[16];
    const float* pp1_g = (const float*)d_in[17];
    const float* pp1_be = (const float*)d_in[18];
    const float* pp2_W = (const float*)d_in[19];
    const float* pp2_b = (const float*)d_in[20];
    const float* pp2_g = (const float*)d_in[21];
    const float* pp2_be = (const float*)d_in[22];
    const float* m1_W = (const float*)d_in[23];
    const float* m1_b = (const float*)d_in[24];
    const float* m1_g = (const float*)d_in[25];
    const float* m1_be = (const float*)d_in[26];
    const float* m2_W = (const float*)d_in[27];
    const float* m2_b = (const float*)d_in[28];
    const float* m2_g = (const float*)d_in[29];
    const float* m2_be = (const float*)d_in[30];
    float* out = (float*)d_out;

    int gl_smem = GL_TOT * sizeof(float);
    cudaFuncSetAttribute(gates_lstm<0>, cudaFuncAttributeMaxDynamicSharedMemorySize, gl_smem);
    cudaFuncSetAttribute(gates_lstm<1>, cudaFuncAttributeMaxDynamicSharedMemorySize, gl_smem);
    cudaFuncSetAttribute(pool_gemm, cudaFuncAttributeMaxDynamicSharedMemorySize, POOL_SMEM);
    cudaFuncSetAttribute(wmma_gemm<1>, cudaFuncAttributeMaxDynamicSharedMemorySize, 36864);
    cudaFuncSetAttribute(wmma_gemm<2>, cudaFuncAttributeMaxDynamicSharedMemorySize, 69632);

    init_state<<<(NT * HD + 255) / 256, 256>>>(h0, c0, last_pos, last_pos_rel, emb_W, emb_b);
    fold_pp1<<<2, 256>>>(pp1_W, pp1_b, pp1_g, pp1_be, sp_W, sp_b);
    fold_LW<<<96, 256>>>(Wih, Whh, bih, bhh);
    prep_wB<0><<<512, 256>>>(pp2_W, pp2_b, pp2_g, pp2_be);
    prep_wB<1><<<512, 256>>>(m1_W, m1_b, m1_g, m1_be);
    prep_wB<2><<<128, 256>>>(m2_W, m2_b, m2_g, m2_be);

    for (int t = 0; t < TS; t++) {
        if (t == 0) gates_lstm<1><<<32, 256, gl_smem>>>(pos_W, pos_b, emb_W, emb_b,
                                                        out + (size_t)t * NT * 2);
        else        gates_lstm<0><<<32, 256, gl_smem>>>(pos_W, pos_b, emb_W, emb_b,
                                                        out + (size_t)t * NT * 2);
        hpre_gemm<<<dim3(4, NT / 32), 256>>>();                    // hpre
        build_x1<<<dim3(8, 8, SC), 256>>>();                       // x1 fp16 tiles
        pool_gemm<<<dim3(4, 256), 256, POOL_SMEM>>>();             // pool (N=256/CTA)
        wmma_gemm<1><<<dim3(8, 16), 256, 36864>>>();               // m1
        wmma_gemm<2><<<dim3(4, 8), 256, 69632>>>();                // m2 split-K partials
    }
    (void)in_sizes; (void)n_in; (void)out_size;
}

// round 11
// speedup vs baseline: 1.1903x; 1.1903x over previous
#include <cuda_runtime.h>
#include <cuda_fp16.h>
#include <mma.h>
#include <stdint.h>
#include <math.h>

using namespace nvcuda;

#define NT 1024
#define HD 128
#define ED 64
#define SC 32
#define PP 32
#define B1D 512
#define B2D 1024
#define M1D 1024
#define TS 12
#define KM1 (HD + B2D)   // 1152
#define BN_INV_F 0.9999950000374997f

// ---------------- device state / scratch ----------------
static __device__ float g_h[NT * HD];
static __device__ float g_c[NT * HD];
static __device__ float g_h2[NT * HD];
static __device__ float g_lp[NT * 2];
static __device__ float g_din[NT * ED];
static __device__ float g_gates[NT * 4 * HD];
static __device__ float g_hp[4 * NT * HD];     // m2 split-K partials
// folded scalar weights
static __device__ float g_A[B1D], g_B[B1D], g_bias1[B1D];
static __device__ float g_Wb[HD * B1D];        // TRANSPOSED: [h][col]
static __device__ float g_bias2[B2D], g_bm1[M1D], g_bm2[HD];
static __device__ float g_LW[4 * HD * 192], g_Lb[4 * HD];
// pre-tiled fp16 weights: [nb][chunk64][128r x 64k] tiles (8192 halfs)
static __device__ __half g_W2th[8 * 8 * 8192];
static __device__ __half g_M1th[8 * 18 * 8192];
static __device__ __half g_M2th[16 * 8192];
// activation tiles, fp16, [group][chunk64][128x64]
static __device__ __half g_x1h[256 * 8 * 8192];   // pool A
static __device__ __half g_mAh[8 * 18 * 8192];    // m1 A
static __device__ __half g_mBh[8 * 16 * 8192];    // m2 A

// ---------------- helpers ----------------
__device__ __forceinline__ uint32_t pack2hf(float v0, float v1) {
    __half2 h = __floats2half2_rn(v0, v1);
    return *(uint32_t*)&h;
}
__device__ __forceinline__ uint32_t smem_u32(const void* p) {
    uint32_t a;
    asm("{ .reg .u64 t; cvta.to.shared.u64 t, %1; cvt.u32.u64 %0, t; }" : "=r"(a) : "l"(p));
    return a;
}
__device__ __forceinline__ void cpa(uint32_t dsmem, const void* gsrc) {
    asm volatile("cp.async.cg.shared.global [%0], [%1], 16;" :: "r"(dsmem), "l"(gsrc) : "memory");
}
#define CPA_COMMIT() asm volatile("cp.async.commit_group;" ::: "memory")
#define CPA_WAIT1()  asm volatile("cp.async.wait_group 1;" ::: "memory")
#define CPA_WAIT0()  asm volatile("cp.async.wait_group 0;" ::: "memory")

// ---------------- prep kernels (once per launch) ----------------
__global__ void init_state(const float* __restrict__ h0, const float* __restrict__ c0,
                           const float* __restrict__ last_pos, const float* __restrict__ last_pos_rel,
                           const float* __restrict__ embW, const float* __restrict__ embb) {
    int idx = blockIdx.x * blockDim.x + threadIdx.x;
    if (idx < NT * HD) { g_h[idx] = h0[idx]; g_c[idx] = c0[idx]; }
    if (idx < NT * 2) g_lp[idx] = last_pos[idx];
    if (idx < NT * ED) {
        int n = idx / ED, e = idx % ED;
        g_din[idx] = last_pos_rel[n * 2] * embW[e * 2] +
                     last_pos_rel[n * 2 + 1] * embW[e * 2 + 1] + embb[e];
    }
}

__global__ void fold_pp1(const float* __restrict__ pp1_W, const float* __restrict__ pp1_b,
                         const float* __restrict__ pp1_g, const float* __restrict__ pp1_be,
                         const float* __restrict__ sp_W, const float* __restrict__ sp_b) {
    int k = blockIdx.x * blockDim.x + threadIdx.x;
    if (k >= B1D) return;
    float s1 = BN_INV_F * pp1_g[k];
    const float* row = pp1_W + (size_t)k * (ED + HD);
    float sa = 0.f, sb = 0.f, sc = 0.f;
    for (int e = 0; e < ED; e++) {
        float w = row[e];
        sa += w * sp_W[e * 2]; sb += w * sp_W[e * 2 + 1]; sc += w * sp_b[e];
    }
    g_A[k] = sa * s1; g_B[k] = sb * s1;
    g_bias1[k] = (pp1_b[k] + sc) * s1 + pp1_be[k];
    for (int h = 0; h < HD; h++) g_Wb[h * B1D + k] = row[ED + h] * s1;   // transposed
}

__global__ void fold_LW(const float* __restrict__ Wih, const float* __restrict__ Whh,
                        const float* __restrict__ bih, const float* __restrict__ bhh) {
    for (int idx = blockIdx.x * blockDim.x + threadIdx.x; idx < 512 * 192; idx += gridDim.x * blockDim.x) {
        int r = idx / 192, cc = idx % 192;
        g_LW[idx] = (cc < 64) ? Wih[r * 64 + cc] : Whh[r * 128 + cc - 64];
        if (cc == 0) g_Lb[r] = bih[r] + bhh[r];
    }
}

// fp16 pre-tiled weights. WM=0: W2(K=512), 1: m1(K=1152), 2: m2(K=1024,R=128)
template <int WM>
__global__ void prep_wB(const float* __restrict__ W, const float* __restrict__ b,
                        const float* __restrict__ g, const float* __restrict__ be) {
    constexpr int K = (WM == 0) ? B1D : (WM == 1) ? KM1 : M1D;
    constexpr int ROWS = (WM == 2) ? HD : 1024;
    constexpr int KC = K / 64;
    __half* oh = (WM == 0) ? g_W2th : (WM == 1) ? g_M1th : g_M2th;
    float* bo = (WM == 0) ? g_bias2 : (WM == 1) ? g_bm1 : g_bm2;
    int total = ROWS * (K / 2);
    for (int p = blockIdx.x * blockDim.x + threadIdx.x; p < total; p += gridDim.x * blockDim.x) {
        int co = p / (K / 2), kp = p % (K / 2), k = kp * 2;
        int nb = co >> 7, r = co & 127, c = k >> 6;
        float s = BN_INV_F * g[co];
        float v0 = W[(size_t)co * K + k] * s, v1 = W[(size_t)co * K + k + 1] * s;
        size_t woff = (size_t)(nb * KC + c) * 4096 + r * 32 + (kp & 31);
        ((uint32_t*)oh)[woff] = pack2hf(v0, v1);
        if (kp == 0) bo[co] = b[co] * s + be[co];
    }
}

// ---------------- gates GEMM (K=192) ----------------
template <int FIRST>
__global__ __launch_bounds__(256) void gates_gemm() {
    int c0 = blockIdx.x * 128, grp = blockIdx.y, tid = threadIdx.x;
    int tx = tid & 31, ty = tid >> 5;
    __shared__ float a_s[32][64];
    __shared__ float w_s[64][129];
    int nbase = grp * 32;
    float acc[4][4] = {};
    for (int k0 = 0; k0 < 192; k0 += 64) {
        __syncthreads();
        for (int idx = tid; idx < 32 * 64; idx += 256) {
            int j = idx >> 6, k = idx & 63, kk = k0 + k;
            float v;
            if (kk < 64) v = g_din[(nbase + j) * ED + kk];
            else {
                int ped = nbase + j, cc = kk - 64;
                if (FIRST) v = g_h[ped * HD + cc];
                else {
                    float sum = g_hp[(size_t)ped * HD + cc]
                              + g_hp[(size_t)(NT + ped) * HD + cc]
                              + g_hp[(size_t)(2 * NT + ped) * HD + cc]
                              + g_hp[(size_t)(3 * NT + ped) * HD + cc];
                    v = fmaxf(sum + g_bm2[cc], 0.f);
                }
            }
            a_s[j][k] = v;
        }
        for (int idx = tid; idx < 128 * 64; idx += 256) {
            int c = idx >> 6, k = idx & 63;
            w_s[k][c] = g_LW[(size_t)(c0 + c) * 192 + k0 + k];
        }
        __syncthreads();
#pragma unroll 4
        for (int k = 0; k < 64; k++) {
            float xr[4], wr[4];
#pragma unroll
            for (int jj = 0; jj < 4; jj++) xr[jj] = a_s[ty + jj * 8][k];
#pragma unroll
            for (int cc = 0; cc < 4; cc++) wr[cc] = w_s[k][tx + cc * 32];
#pragma unroll
            for (int jj = 0; jj < 4; jj++)
#pragma unroll
                for (int cc = 0; cc < 4; cc++) acc[jj][cc] = fmaf(xr[jj], wr[cc], acc[jj][cc]);
        }
    }
#pragma unroll
    for (int jj = 0; jj < 4; jj++) {
        int n = nbase + ty + jj * 8;
#pragma unroll
        for (int cc = 0; cc < 4; cc++) {
            int c = c0 + tx + cc * 32;
            g_gates[(size_t)n * 512 + c] = acc[jj][cc] + g_Lb[c];
        }
    }
}

// ---------------- LSTM pointwise + h2 pack into m1 A-tiles ----------------
__global__ __launch_bounds__(128) void lstm_point(
    const float* __restrict__ posW, const float* __restrict__ posb,
    const float* __restrict__ embW, const float* __restrict__ embb,
    float* __restrict__ out_t) {
    int n = blockIdx.x, t = threadIdx.x;
    __shared__ float red0[HD], red1[HD], hs2[HD], rp[2];
    float gi = g_gates[n * 512 + 0 * HD + t];
    float gf = g_gates[n * 512 + 1 * HD + t];
    float gg = g_gates[n * 512 + 2 * HD + t];
    float go = g_gates[n * 512 + 3 * HD + t];
    float ig = 1.f / (1.f + expf(-gi));
    float fg = 1.f / (1.f + expf(-gf));
    float gv = tanhf(gg);
    float og = 1.f / (1.f + expf(-go));
    float c2 = fg * g_c[n * HD + t] + ig * gv;
    float h2 = og * tanhf(c2);
    g_c[n * HD + t] = c2;
    g_h2[n * HD + t] = h2;
    hs2[t] = h2;
    red0[t] = h2 * posW[t]; red1[t] = h2 * posW[HD + t];
    __syncthreads();
    for (int s = 64; s > 0; s >>= 1) {
        if (t < s) { red0[t] += red0[t + s]; red1[t] += red1[t + s]; }
        __syncthreads();
    }
    if (t < 2) {
        float v = ((t == 0) ? red0[0] : red1[0]) + posb[t];
        rp[t] = v;
        out_t[n * 2 + t] = v;
        g_lp[n * 2 + t] += v;
    }
    __syncthreads();
    if (t < ED) g_din[n * ED + t] = fmaf(rp[0], embW[t * 2], fmaf(rp[1], embW[t * 2 + 1], embb[t]));
    if (t < 64) {
        int mb = n >> 7, m = n & 127;
        int c = t >> 5;
        ((uint32_t*)g_mAh)[(size_t)(mb * 18 + c) * 4096 + m * 32 + (t & 31)] =
            pack2hf(hs2[2 * t], hs2[2 * t + 1]);
    }
}

// ---------------- fused hpre GEMM + x1 tile build ----------------
// grid (8 kc, 32 s), 256 threads. Computes hpre slice (32 peds x 64 cols, K=128)
// in smem, then emits x1 fp16 tiles for all 8 i-blocks of the scene.
// dyn smem (floats): h2s 32x129 | Wbs 128x65 | hps 32x65 | rxs 1024 | rys 1024 | A/B/b1 192
#define HB_H2   0
#define HB_WB   (32 * 129)
#define HB_HP   (HB_WB + 128 * 65)
#define HB_RX   (HB_HP + 32 * 65)
#define HB_RY   (HB_RX + 1024)
#define HB_AB   (HB_RY + 1024)
#define HB_TOT  (HB_AB + 192)

__global__ __launch_bounds__(256) void hb_fused() {
    extern __shared__ float sm[];
    float* h2s = sm + HB_H2;
    float* Wbs = sm + HB_WB;
    float* hps = sm + HB_HP;
    float* rxs = sm + HB_RX;
    float* rys = sm + HB_RY;
    float* As  = sm + HB_AB;
    float* Bs  = As + 64;
    float* b1s = As + 128;
    int kc = blockIdx.x, s = blockIdx.y;
    int tid = threadIdx.x;

    for (int idx = tid; idx < 32 * 128; idx += 256) {
        int j = idx >> 7, h = idx & 127;
        h2s[j * 129 + h] = g_h2[(s * 32 + j) * HD + h];
    }
    for (int idx = tid; idx < 128 * 64; idx += 256) {
        int h = idx >> 6, c = idx & 63;
        Wbs[h * 65 + c] = g_Wb[h * B1D + kc * 64 + c];
    }
    if (tid < 64) {
        As[tid]  = g_A[kc * 64 + tid];
        Bs[tid]  = g_B[kc * 64 + tid];
        b1s[tid] = g_bias1[kc * 64 + tid];
    }
    for (int idx = tid; idx < 1024; idx += 256) {
        int i = idx >> 5, j = idx & 31;
        float dx = g_lp[(s * 32 + j) * 2]     - g_lp[(s * 32 + i) * 2];
        float dy = g_lp[(s * 32 + j) * 2 + 1] - g_lp[(s * 32 + i) * 2 + 1];
        float nrm = fmaxf(sqrtf(dx * dx + dy * dy), 1e-12f);
        rxs[idx] = dx / nrm; rys[idx] = dy / nrm;
    }
    __syncthreads();

    // hpre GEMM: thread (j = tid>>3, cg = tid&7) computes cols c = cg + cc*8
    {
        int j = tid >> 3, cg = tid & 7;
        float acc[8] = {};
#pragma unroll 4
        for (int h = 0; h < 128; h++) {
            float a = h2s[j * 129 + h];
#pragma unroll
            for (int cc = 0; cc < 8; cc++)
                acc[cc] = fmaf(a, Wbs[h * 65 + cg + cc * 8], acc[cc]);
        }
#pragma unroll
        for (int cc = 0; cc < 8; cc++) {
            int c = cg + cc * 8;
            hps[j * 65 + c] = acc[cc] + b1s[c];
        }
    }
    __syncthreads();

    // emit x1 tiles: per q, each warp writes one contiguous 128B row
    int kp = tid & 31;
    float a0 = As[2 * kp], a1 = As[2 * kp + 1];
    float b0 = Bs[2 * kp], b1 = Bs[2 * kp + 1];
    for (int ib = 0; ib < 8; ib++) {
        uint32_t* oh = (uint32_t*)g_x1h + (size_t)((s * 8 + ib) * 8 + kc) * 4096;
#pragma unroll
        for (int q = 0; q < 16; q++) {
            int m = (tid >> 5) + q * 8;
            int j = m & 31, il = m >> 5, i = ib * 4 + il;
            float h0 = hps[j * 65 + 2 * kp], h1 = hps[j * 65 + 2 * kp + 1];
            float rx = rxs[i * 32 + j], ry = rys[i * 32 + j];
            float v0 = fmaxf(h0 + rx * a0 + ry * b0, 0.f);
            float v1 = fmaxf(h1 + rx * a1 + ry * b1, 0.f);
            oh[m * 32 + kp] = pack2hf(v0, v1);
        }
    }
}

// ---------------- wmma fp16 single-pass GEMM with cp.async pipeline (R9) ----------------
// GM=0: pool, grid(8 nb, 128), GROUPS=2 (M=2x128), KC=16, warp tile 32x64
// GM=1: m1,   grid(8 nb, 16),  GROUPS=1, ROWS=64, KC=36, warp tile 32x32
// GM=2: m2,   grid(4 ksl, 8),  GROUPS=1, ROWS=128, KC=8, warp tile 32x64
template <int GM>
__global__ __launch_bounds__(256) void wmma_gemm() {
    constexpr int KC = (GM == 0) ? 16 : (GM == 1) ? 36 : 8;
    constexpr int GROUPS = (GM == 0) ? 2 : 1;
    constexpr int ROWS = (GM == 1) ? 64 : 128;
    constexpr int NF = (GM == 1) ? 2 : 4;
    constexpr int WC = (GM == 1) ? 4 : 2;
    constexpr int SA = ROWS * 80;
    constexpr int SS = GROUPS * SA + 10240;
    extern __shared__ __align__(16) char smraw[];
    uint32_t base = smem_u32(smraw);
    float* c_s = (float*)smraw;

    int tid = threadIdx.x, w = tid >> 5;
    int wr = w / WC, wc = w % WC;
    int nbX = blockIdx.x, grpY = blockIdx.y;

    const __half* Ah_g = (GM == 0) ? g_x1h : (GM == 1) ? g_mAh : g_mBh;
    const __half* Wh_g = (GM == 0) ? g_W2th : (GM == 1) ? g_M1th : g_M2th;

    auto stage = [&](int buf, int c) {
        int tile0 = 0, tile1 = 0, sub, roff = 0, wtile;
        if (GM == 0) {
            int ch = c >> 1; sub = c & 1;
            tile0 = (grpY * 2) * 8 + ch; tile1 = (grpY * 2 + 1) * 8 + ch;
            wtile = nbX * 8 + ch;
        } else if (GM == 1) {
            int ch = c >> 1; sub = c & 1;
            tile0 = (grpY >> 1) * 18 + ch; roff = (grpY & 1) * 64;
            wtile = nbX * 18 + ch;
        } else {
            int gch = nbX * 8 + c; sub = gch & 1;
            tile0 = grpY * 16 + (gch >> 1);
            wtile = gch >> 1;
        }
        uint32_t sb = base + buf * SS;
        for (int i = tid; i < GROUPS * ROWS * 4; i += 256) {
            int g = i / (ROWS * 4), r = (i >> 2) % ROWS, seg = i & 3;
            int tile = g ? tile1 : tile0;
            size_t so = (size_t)tile * 8192 + (roff + r) * 64 + sub * 32 + seg * 8;
            cpa(sb + g * SA + r * 80 + seg * 16, Ah_g + so);
        }
        for (int i = tid; i < 512; i += 256) {
            int r = i >> 2, seg = i & 3;
            size_t so = (size_t)wtile * 8192 + r * 64 + sub * 32 + seg * 8;
            cpa(sb + GROUPS * SA + r * 80 + seg * 16, Wh_g + so);
        }
        CPA_COMMIT();
    };

    wmma::fragment<wmma::accumulator, 16, 16, 16, float> acc[GROUPS][2][NF];
#pragma unroll
    for (int g = 0; g < GROUPS; g++)
#pragma unroll
        for (int mf = 0; mf < 2; mf++)
#pragma unroll
            for (int nf = 0; nf < NF; nf++) wmma::fill_fragment(acc[g][mf][nf], 0.f);

    stage(0, 0);
    for (int c = 0; c < KC; c++) {
        if (c + 1 < KC) { stage((c + 1) & 1, c + 1); CPA_WAIT1(); } else { CPA_WAIT0(); }
        __syncthreads();
        const __half* sbuf = (const __half*)(smraw + (c & 1) * SS);
        const __half* whp = sbuf + (GROUPS * SA) / 2;
#pragma unroll
        for (int ks = 0; ks < 2; ks++) {
            wmma::fragment<wmma::matrix_a, 16, 16, 16, __half, wmma::row_major> af[GROUPS][2];
#pragma unroll
            for (int g = 0; g < GROUPS; g++)
#pragma unroll
                for (int mf = 0; mf < 2; mf++)
                    wmma::load_matrix_sync(af[g][mf],
                        sbuf + g * (SA / 2) + (wr * 32 + mf * 16) * 40 + ks * 16, 40);
#pragma unroll
            for (int nf = 0; nf < NF; nf++) {
                wmma::fragment<wmma::matrix_b, 16, 16, 16, __half, wmma::col_major> bh;
                int coff = (wc * NF * 16 + nf * 16) * 40 + ks * 16;
                wmma::load_matrix_sync(bh, whp + coff, 40);
#pragma unroll
                for (int g = 0; g < GROUPS; g++)
#pragma unroll
                    for (int mf = 0; mf < 2; mf++)
                        wmma::mma_sync(acc[g][mf][nf], af[g][mf], bh, acc[g][mf][nf]);
            }
        }
        __syncthreads();
    }

    for (int g = 0; g < GROUPS; g++) {
        __syncthreads();
#pragma unroll
        for (int mf = 0; mf < 2; mf++)
#pragma unroll
            for (int nf = 0; nf < NF; nf++)
                wmma::store_matrix_sync(c_s + (wr * 32 + mf * 16) * 136 + wc * NF * 16 + nf * 16,
                                        acc[g][mf][nf], 136, wmma::mem_row_major);
        __syncthreads();

        if (GM == 0) {
            int grp = grpY * 2 + g;
            int s = grp >> 3, ib = grp & 7;
            if (tid < 256) {
                int il = tid >> 6, kp0 = tid & 63;
                int cc0 = kp0 * 2;
                float m0 = c_s[(il * 32) * 136 + cc0];
                float m1v = c_s[(il * 32) * 136 + cc0 + 1];
#pragma unroll 8
                for (int r = 1; r < 32; r++) {
                    m0  = fmaxf(m0,  c_s[(il * 32 + r) * 136 + cc0]);
                    m1v = fmaxf(m1v, c_s[(il * 32 + r) * 136 + cc0 + 1]);
                }
                int col = nbX * 128 + cc0;
                float v0 = fmaxf(m0 + g_bias2[col], 0.f);
                float v1 = fmaxf(m1v + g_bias2[col + 1], 0.f);
                int ped = s * 32 + ib * 4 + il;
                int mb = ped >> 7, m = ped & 127;
                int cch = 2 + nbX * 2 + (kp0 >> 5);
                ((uint32_t*)g_mAh)[(size_t)(mb * 18 + cch) * 4096 + m * 32 + (kp0 & 31)] =
                    pack2hf(v0, v1);
            }
        } else if (GM == 1) {
            for (int p = tid; p < 4096; p += 256) {
                int r = p >> 6, kp = p & 63;
                int cc0 = kp * 2, col = nbX * 128 + cc0;
                float v0 = fmaxf(c_s[r * 136 + cc0]     + g_bm1[col], 0.f);
                float v1 = fmaxf(c_s[r * 136 + cc0 + 1] + g_bm1[col + 1], 0.f);
                int ped = grpY * 64 + r;
                int mb = ped >> 7, m = ped & 127;
                int cch = nbX * 2 + (kp >> 5);
                ((uint32_t*)g_mBh)[(size_t)(mb * 16 + cch) * 4096 + m * 32 + (kp & 31)] =
                    pack2hf(v0, v1);
            }
        } else {
            float* dst = g_hp + (size_t)nbX * NT * HD + (size_t)grpY * 128 * HD;
            for (int p = tid; p < 16384; p += 256) {
                int r = p >> 7, cc = p & 127;
                dst[r * HD + cc] = c_s[r * 136 + cc];
            }
        }
    }
}

// ---------------- host launch ----------------
extern "C" void kernel_launch(void* const* d_in, const int* in_sizes, int n_in,
                              void* d_out, int out_size) {
    const float* last_pos     = (const float*)d_in[0];
    const float* last_pos_rel = (const float*)d_in[1];
    const float* h0  = (const float*)d_in[2];
    const float* c0  = (const float*)d_in[3];
    const float* emb_W = (const float*)d_in[5];
    const float* emb_b = (const float*)d_in[6];
    const float* Wih = (const float*)d_in[7];
    const float* Whh = (const float*)d_in[8];
    const float* bih = (const float*)d_in[9];
    const float* bhh = (const float*)d_in[10];
    const float* pos_W = (const float*)d_in[11];
    const float* pos_b = (const float*)d_in[12];
    const float* sp_W = (const float*)d_in[13];
    const float* sp_b = (const float*)d_in[14];
    const float* pp1_W = (const float*)d_in[15];
    const float* pp1_b = (const float*)d_in[16];
    const float* pp1_g = (const float*)d_in[17];
    const float* pp1_be = (const float*)d_in[18];
    const float* pp2_W = (const float*)d_in[19];
    const float* pp2_b = (const float*)d_in[20];
    const float* pp2_g = (const float*)d_in[21];
    const float* pp2_be = (const float*)d_in[22];
    const float* m1_W = (const float*)d_in[23];
    const float* m1_b = (const float*)d_in[24];
    const float* m1_g = (const float*)d_in[25];
    const float* m1_be = (const float*)d_in[26];
    const float* m2_W = (const float*)d_in[27];
    const float* m2_b = (const float*)d_in[28];
    const float* m2_g = (const float*)d_in[29];
    const float* m2_be = (const float*)d_in[30];
    float* out = (float*)d_out;

    int hb_smem = HB_TOT * sizeof(float);
    cudaFuncSetAttribute(hb_fused, cudaFuncAttributeMaxDynamicSharedMemorySize, hb_smem);
    cudaFuncSetAttribute(wmma_gemm<0>, cudaFuncAttributeMaxDynamicSharedMemorySize, 69632);
    cudaFuncSetAttribute(wmma_gemm<1>, cudaFuncAttributeMaxDynamicSharedMemorySize, 36864);
    cudaFuncSetAttribute(wmma_gemm<2>, cudaFuncAttributeMaxDynamicSharedMemorySize, 69632);

    init_state<<<(NT * HD + 255) / 256, 256>>>(h0, c0, last_pos, last_pos_rel, emb_W, emb_b);
    fold_pp1<<<2, 256>>>(pp1_W, pp1_b, pp1_g, pp1_be, sp_W, sp_b);
    fold_LW<<<96, 256>>>(Wih, Whh, bih, bhh);
    prep_wB<0><<<512, 256>>>(pp2_W, pp2_b, pp2_g, pp2_be);
    prep_wB<1><<<512, 256>>>(m1_W, m1_b, m1_g, m1_be);
    prep_wB<2><<<128, 256>>>(m2_W, m2_b, m2_g, m2_be);

    for (int t = 0; t < TS; t++) {
        if (t == 0) gates_gemm<1><<<dim3(4, NT / 32), 256>>>();
        else        gates_gemm<0><<<dim3(4, NT / 32), 256>>>();
        lstm_point<<<NT, 128>>>(pos_W, pos_b, emb_W, emb_b, out + (size_t)t * NT * 2);
        hb_fused<<<dim3(8, SC), 256, hb_smem>>>();                 // hpre + x1 tiles fused
        wmma_gemm<0><<<dim3(8, 128), 256, 69632>>>();              // pool
        wmma_gemm<1><<<dim3(8, 16), 256, 36864>>>();               // m1
        wmma_gemm<2><<<dim3(4, 8), 256, 69632>>>();                // m2 split-K partials
    }
    (void)in_sizes; (void)n_in; (void)out_size;
}